// round 2
// baseline (speedup 1.0000x reference)
#include <cuda_runtime.h>
#include <cstdint>
#include <math.h>

// ============================================================================
// GaussianMixtureModel sampling: replicate JAX threefry2x32 (partitionable
// mode) + gumbel categorical + erfinv normals + per-component Cholesky.
//
// out[n,f] = means[idx_n, f] + sum_{j<=f} L[idx_n][f][j] * z[n,j]
// ============================================================================

#define N_COMP 16
#define N_FEAT 32

// -------------------- threefry2x32 --------------------
// Host rotate
static inline uint32_t h_rotl(uint32_t x, int r) { return (x << r) | (x >> (32 - r)); }

static inline void h_threefry(uint32_t k0, uint32_t k1, uint32_t x0, uint32_t x1,
                              uint32_t* o0, uint32_t* o1) {
    uint32_t k2 = k0 ^ k1 ^ 0x1BD11BDAu;
#define HR_(r) { x0 += x1; x1 = h_rotl(x1, r); x1 ^= x0; }
    x0 += k0; x1 += k1;
    HR_(13) HR_(15) HR_(26) HR_(6)
    x0 += k1; x1 += k2 + 1u;
    HR_(17) HR_(29) HR_(16) HR_(24)
    x0 += k2; x1 += k0 + 2u;
    HR_(13) HR_(15) HR_(26) HR_(6)
    x0 += k0; x1 += k1 + 3u;
    HR_(17) HR_(29) HR_(16) HR_(24)
    x0 += k1; x1 += k2 + 4u;
    HR_(13) HR_(15) HR_(26) HR_(6)
    x0 += k2; x1 += k0 + 5u;
#undef HR_
    *o0 = x0; *o1 = x1;
}

// Device: returns out0 ^ out1 (partitionable 32-bit random word)
__device__ __forceinline__ uint32_t d_threefry_xor(uint32_t k0, uint32_t k1,
                                                   uint32_t x0, uint32_t x1) {
    uint32_t k2 = k0 ^ k1 ^ 0x1BD11BDAu;
#define DR_(r) { x0 += x1; x1 = __funnelshift_l(x1, x1, r); x1 ^= x0; }
    x0 += k0; x1 += k1;
    DR_(13) DR_(15) DR_(26) DR_(6)
    x0 += k1; x1 += k2 + 1u;
    DR_(17) DR_(29) DR_(16) DR_(24)
    x0 += k2; x1 += k0 + 2u;
    DR_(13) DR_(15) DR_(26) DR_(6)
    x0 += k0; x1 += k1 + 3u;
    DR_(17) DR_(29) DR_(16) DR_(24)
    x0 += k1; x1 += k2 + 4u;
    DR_(13) DR_(15) DR_(26) DR_(6)
    x0 += k2; x1 += k0 + 5u;
#undef DR_
    return x0 ^ x1;
}

// -------------------- XLA erfinv (Giles approximation, f32) --------------------
__device__ __forceinline__ float erfinv_xla(float x) {
    float w = -log1pf(-x * x);
    float p;
    if (w < 5.0f) {
        w = w - 2.5f;
        p = 2.81022636e-08f;
        p = fmaf(p, w, 3.43273939e-07f);
        p = fmaf(p, w, -3.5233877e-06f);
        p = fmaf(p, w, -4.39150654e-06f);
        p = fmaf(p, w, 0.00021858087f);
        p = fmaf(p, w, -0.00125372503f);
        p = fmaf(p, w, -0.00417768164f);
        p = fmaf(p, w, 0.246640727f);
        p = fmaf(p, w, 1.50140941f);
    } else {
        w = sqrtf(w) - 3.0f;
        p = -0.000200214257f;
        p = fmaf(p, w, 0.000100950558f);
        p = fmaf(p, w, 0.00134934322f);
        p = fmaf(p, w, -0.00367342844f);
        p = fmaf(p, w, 0.00573950773f);
        p = fmaf(p, w, -0.0076224613f);
        p = fmaf(p, w, 0.00943887047f);
        p = fmaf(p, w, 1.00167406f);
        p = fmaf(p, w, 2.83297682f);
    }
    return p * x;
}

// -------------------- device scratch --------------------
// Packed lower-triangular Cholesky factors: g_L[k*528 + f*(f+1)/2 + j]
__device__ float g_L[N_COMP * 528];
__device__ float g_logits[N_COMP];

// -------------------- prep kernel: cholesky + logits --------------------
__global__ void gmm_prep_kernel(const float* __restrict__ w,
                                const float* __restrict__ covs) {
    int warp = threadIdx.x >> 5;
    int lane = threadIdx.x & 31;

    if (threadIdx.x < N_COMP) g_logits[threadIdx.x] = logf(w[threadIdx.x]);
    if (warp >= N_COMP) return;

    // thread `lane` of warp `warp` owns row `lane` of component `warp`.
    float row[32];
    const float* A = covs + warp * (N_FEAT * N_FEAT) + lane * N_FEAT;
#pragma unroll
    for (int j = 0; j < 32; j++) row[j] = A[j];

#pragma unroll
    for (int j = 0; j < 32; j++) {
        float diag = __shfl_sync(0xffffffffu, row[j], j);
        float Ljj = sqrtf(diag);
        float val = row[j] / Ljj;          // rows below diag
        if (lane == j) val = Ljj;
        if (lane < j) val = 0.0f;
        row[j] = val;
        // trailing rank-1 update: row[m] -= l[lane] * l[m]
#pragma unroll
        for (int m = j + 1; m < 32; m++) {
            float lm = __shfl_sync(0xffffffffu, val, m);
            row[m] -= val * lm;
        }
    }

    // store packed lower triangle
    int base = warp * 528 + lane * (lane + 1) / 2;
#pragma unroll
    for (int j = 0; j < 32; j++) {
        if (j <= lane) g_L[base + j] = row[j];
    }
}

// -------------------- main kernel --------------------
#define LSTRIDE 529   // 529 mod 32 = 17 (odd) -> conflict-free across component idx
#define MSTRIDE 33

__global__ void __launch_bounds__(256)
gmm_main_kernel(const float* __restrict__ means, float* __restrict__ out, int N,
                uint32_t kc0, uint32_t kc1, uint32_t kz0, uint32_t kz1) {
    __shared__ float L_sh[N_COMP * LSTRIDE];
    __shared__ float mean_sh[N_COMP * MSTRIDE];
    __shared__ float logit_sh[N_COMP];

    // cooperative loads
    for (int i = threadIdx.x; i < N_COMP * 528; i += blockDim.x) {
        int k = i / 528, r = i - k * 528;
        L_sh[k * LSTRIDE + r] = g_L[i];
    }
    for (int i = threadIdx.x; i < N_COMP * N_FEAT; i += blockDim.x) {
        mean_sh[(i >> 5) * MSTRIDE + (i & 31)] = means[i];
    }
    if (threadIdx.x < N_COMP) logit_sh[threadIdx.x] = g_logits[threadIdx.x];
    __syncthreads();

    int n = blockIdx.x * blockDim.x + threadIdx.x;
    if (n >= N) return;

    // ---- categorical: argmax_k logit_k + gumbel(u_{n,k}) ----
    const float TINY = 1.17549435e-38f;
    uint32_t e0 = (uint32_t)n * 16u;
    int best_k = 0;
    float best = __int_as_float(0xff800000); // -inf
#pragma unroll 4
    for (int k = 0; k < N_COMP; k++) {
        uint32_t b = d_threefry_xor(kc0, kc1, 0u, e0 + (uint32_t)k);
        float u = __uint_as_float((b >> 9) | 0x3f800000u) - 1.0f;
        u = fmaxf(u, TINY);                  // == max(tiny, u*(1-tiny)+tiny) in f32
        float g = -logf(-logf(u));
        float s = g + logit_sh[k];
        if (s > best) { best = s; best_k = k; }
    }

    // ---- normals: z_f = sqrt(2) * erfinv(u*2 - 0.99999994) ----
    float z[32];
    uint32_t e1 = (uint32_t)n * 32u;
#pragma unroll 4
    for (int f = 0; f < 32; f++) {
        uint32_t b = d_threefry_xor(kz0, kz1, 0u, e1 + (uint32_t)f);
        float u = __uint_as_float((b >> 9) | 0x3f800000u) - 1.0f;
        // maxval - minval rounds to exactly 2.0f; then clamp at minval
        float x = fmaxf(u * 2.0f + (-0.99999994f), -0.99999994f);
        z[f] = 1.41421356237309515f * erfinv_xla(x);
    }

    // ---- out[n,f] = mean[idx,f] + sum_{j<=f} L[idx][f][j] z[j] ----
    const int lbase = best_k * LSTRIDE;
    const int mbase = best_k * MSTRIDE;
    float* outp = out + (size_t)n * N_FEAT;
    int tri = 0;
#pragma unroll
    for (int f0 = 0; f0 < 32; f0 += 4) {
        float acc[4];
#pragma unroll
        for (int q = 0; q < 4; q++) {
            int f = f0 + q;
            float a = mean_sh[mbase + f];
#pragma unroll
            for (int j = 0; j <= f; j++) {
                a = fmaf(z[j], L_sh[lbase + tri + j], a);
            }
            tri += f + 1;
            acc[q] = a;
        }
        // streaming store: output is write-once, never re-read -> don't pollute L2
        __stcs(reinterpret_cast<float4*>(outp + f0),
               make_float4(acc[0], acc[1], acc[2], acc[3]));
    }
}

// -------------------- launch --------------------
extern "C" void kernel_launch(void* const* d_in, const int* in_sizes, int n_in,
                              void* d_out, int out_size) {
    // identify inputs by element count (n_samples=1, weights=16, means=512, covs=16384)
    const float* w = nullptr;
    const float* means = nullptr;
    const float* covs = nullptr;
    for (int i = 0; i < n_in; i++) {
        if (in_sizes[i] == N_COMP) w = (const float*)d_in[i];
        else if (in_sizes[i] == N_COMP * N_FEAT) means = (const float*)d_in[i];
        else if (in_sizes[i] == N_COMP * N_FEAT * N_FEAT) covs = (const float*)d_in[i];
    }

    int N = out_size / N_FEAT;

    // JAX key chain (threefry partitionable):
    // key(42) = (0,42); split -> key_i = full output pair of block with x=(0,i)
    uint32_t kc0, kc1, kz0, kz1;
    h_threefry(0u, 42u, 0u, 0u, &kc0, &kc1);
    h_threefry(0u, 42u, 0u, 1u, &kz0, &kz1);

    gmm_prep_kernel<<<1, 512>>>(w, covs);

    int blocks = (N + 255) / 256;
    gmm_main_kernel<<<blocks, 256>>>(means, (float*)d_out, N, kc0, kc1, kz0, kz1);
}

// round 3
// speedup vs baseline: 1.0982x; 1.0982x over previous
#include <cuda_runtime.h>
#include <cstdint>
#include <math.h>

// ============================================================================
// GaussianMixtureModel sampling: replicate JAX threefry2x32 (partitionable
// mode) + categorical (bits-argmax fast path w/ exact tie fixup) + erfinv
// normals + per-component Cholesky.
//
// out[n,f] = means[idx_n, f] + sum_{j<=f} L[idx_n][f][j] * z[n,j]
// ============================================================================

#define N_COMP 16
#define N_FEAT 32

// -------------------- threefry2x32 --------------------
static inline uint32_t h_rotl(uint32_t x, int r) { return (x << r) | (x >> (32 - r)); }

static inline void h_threefry(uint32_t k0, uint32_t k1, uint32_t x0, uint32_t x1,
                              uint32_t* o0, uint32_t* o1) {
    uint32_t k2 = k0 ^ k1 ^ 0x1BD11BDAu;
#define HR_(r) { x0 += x1; x1 = h_rotl(x1, r); x1 ^= x0; }
    x0 += k0; x1 += k1;
    HR_(13) HR_(15) HR_(26) HR_(6)
    x0 += k1; x1 += k2 + 1u;
    HR_(17) HR_(29) HR_(16) HR_(24)
    x0 += k2; x1 += k0 + 2u;
    HR_(13) HR_(15) HR_(26) HR_(6)
    x0 += k0; x1 += k1 + 3u;
    HR_(17) HR_(29) HR_(16) HR_(24)
    x0 += k1; x1 += k2 + 4u;
    HR_(13) HR_(15) HR_(26) HR_(6)
    x0 += k2; x1 += k0 + 5u;
#undef HR_
    *o0 = x0; *o1 = x1;
}

// Device: returns out0 ^ out1 (partitionable 32-bit random word)
__device__ __forceinline__ uint32_t d_threefry_xor(uint32_t k0, uint32_t k1,
                                                   uint32_t x0, uint32_t x1) {
    uint32_t k2 = k0 ^ k1 ^ 0x1BD11BDAu;
#define DR_(r) { x0 += x1; x1 = __funnelshift_l(x1, x1, r); x1 ^= x0; }
    x0 += k0; x1 += k1;
    DR_(13) DR_(15) DR_(26) DR_(6)
    x0 += k1; x1 += k2 + 1u;
    DR_(17) DR_(29) DR_(16) DR_(24)
    x0 += k2; x1 += k0 + 2u;
    DR_(13) DR_(15) DR_(26) DR_(6)
    x0 += k0; x1 += k1 + 3u;
    DR_(17) DR_(29) DR_(16) DR_(24)
    x0 += k1; x1 += k2 + 4u;
    DR_(13) DR_(15) DR_(26) DR_(6)
    x0 += k2; x1 += k0 + 5u;
#undef DR_
    return x0 ^ x1;
}

// -------------------- fast erfinv (Giles poly; MUFU log, fma for 1-x^2) ------
__device__ __forceinline__ float erfinv_fast(float x) {
    // fmaf(-x,x,1) computes 1-x^2 without catastrophic cancellation.
    float w = -__logf(fmaf(-x, x, 1.0f));
    float p;
    if (w < 5.0f) {
        w = w - 2.5f;
        p = 2.81022636e-08f;
        p = fmaf(p, w, 3.43273939e-07f);
        p = fmaf(p, w, -3.5233877e-06f);
        p = fmaf(p, w, -4.39150654e-06f);
        p = fmaf(p, w, 0.00021858087f);
        p = fmaf(p, w, -0.00125372503f);
        p = fmaf(p, w, -0.00417768164f);
        p = fmaf(p, w, 0.246640727f);
        p = fmaf(p, w, 1.50140941f);
    } else {
        w = sqrtf(w) - 3.0f;
        p = -0.000200214257f;
        p = fmaf(p, w, 0.000100950558f);
        p = fmaf(p, w, 0.00134934322f);
        p = fmaf(p, w, -0.00367342844f);
        p = fmaf(p, w, 0.00573950773f);
        p = fmaf(p, w, -0.0076224613f);
        p = fmaf(p, w, 0.00943887047f);
        p = fmaf(p, w, 1.00167406f);
        p = fmaf(p, w, 2.83297682f);
    }
    return p * x;
}

// -------------------- device scratch --------------------
__device__ float g_L[N_COMP * 528];     // packed lower-tri Cholesky
__device__ float g_logits[N_COMP];
__device__ int   g_uniform;             // 1 if all weights bitwise-equal

// -------------------- prep kernel: cholesky + logits + uniform flag ---------
__global__ void gmm_prep_kernel(const float* __restrict__ w,
                                const float* __restrict__ covs) {
    int warp = threadIdx.x >> 5;
    int lane = threadIdx.x & 31;

    if (threadIdx.x < N_COMP) g_logits[threadIdx.x] = logf(w[threadIdx.x]);
    if (threadIdx.x == 0) {
        int uni = 1;
        for (int k = 1; k < N_COMP; k++)
            if (__float_as_uint(w[k]) != __float_as_uint(w[0])) uni = 0;
        g_uniform = uni;
    }
    if (warp >= N_COMP) return;

    float row[32];
    const float* A = covs + warp * (N_FEAT * N_FEAT) + lane * N_FEAT;
#pragma unroll
    for (int j = 0; j < 32; j++) row[j] = A[j];

#pragma unroll
    for (int j = 0; j < 32; j++) {
        float diag = __shfl_sync(0xffffffffu, row[j], j);
        float Ljj = sqrtf(diag);
        float val = row[j] / Ljj;
        if (lane == j) val = Ljj;
        if (lane < j) val = 0.0f;
        row[j] = val;
#pragma unroll
        for (int m = j + 1; m < 32; m++) {
            float lm = __shfl_sync(0xffffffffu, val, m);
            row[m] -= val * lm;
        }
    }

    int base = warp * 528 + lane * (lane + 1) / 2;
#pragma unroll
    for (int j = 0; j < 32; j++) {
        if (j <= lane) g_L[base + j] = row[j];
    }
}

// -------------------- main kernel --------------------
#define LSTRIDE 529   // 529 mod 32 = 17 (odd) -> conflict-free across component idx
#define MSTRIDE 33

__global__ void __launch_bounds__(256, 2)
gmm_main_kernel(const float* __restrict__ means, float* __restrict__ out, int N,
                uint32_t kc0, uint32_t kc1, uint32_t kz0, uint32_t kz1) {
    __shared__ float L_sh[N_COMP * LSTRIDE];
    __shared__ float mean_sh[N_COMP * MSTRIDE];
    __shared__ float logit_sh[N_COMP];
    __shared__ int   uni_sh;

    for (int i = threadIdx.x; i < N_COMP * 528; i += blockDim.x) {
        int k = i / 528, r = i - k * 528;
        L_sh[k * LSTRIDE + r] = g_L[i];
    }
    for (int i = threadIdx.x; i < N_COMP * N_FEAT; i += blockDim.x) {
        mean_sh[(i >> 5) * MSTRIDE + (i & 31)] = means[i];
    }
    if (threadIdx.x < N_COMP) logit_sh[threadIdx.x] = g_logits[threadIdx.x];
    if (threadIdx.x == 0) uni_sh = g_uniform;
    __syncthreads();

    int n = blockIdx.x * blockDim.x + threadIdx.x;
    if (n >= N) return;

    const float TINY = 1.17549435e-38f;
    uint32_t e0 = (uint32_t)n * 16u;
    int best_k;

    if (uni_sh) {
        // ---- fast categorical: uniform logits cancel; argmax_k u_k over the
        // monotone map u = f(b>>9). Track max + second max (first-index wins).
        uint32_t m1, m2; int j1, j2;
        {
            uint32_t v0 = d_threefry_xor(kc0, kc1, 0u, e0) >> 9;
            m1 = v0; j1 = 0; m2 = 0u; j2 = 99;
        }
#pragma unroll 5
        for (int k = 1; k < N_COMP; k++) {
            uint32_t v = d_threefry_xor(kc0, kc1, 0u, e0 + (uint32_t)k) >> 9;
            if (v > m1)      { m2 = m1; j2 = j1; m1 = v; j1 = k; }
            else if (v > m2) { m2 = v; j2 = k; }
        }
        best_k = j1;
        // Rounding-tie fixup: ref picks earlier index when s_{j2} rounds equal
        // to s_{j1}. Only possible outcome change when j2 < j1.
        if (j2 < j1) {
            float u1 = fmaxf(__uint_as_float(m1 | 0x3f800000u) - 1.0f, TINY);
            float u2 = fmaxf(__uint_as_float(m2 | 0x3f800000u) - 1.0f, TINY);
            float s1 = -logf(-logf(u1)) + logit_sh[j1];
            float s2 = -logf(-logf(u2)) + logit_sh[j2];
            if (s2 >= s1) best_k = j2;
        }
    } else {
        // ---- general path: full gumbel argmax (exactly the R2 kernel) ----
        best_k = 0;
        float best = __int_as_float(0xff800000);
#pragma unroll 4
        for (int k = 0; k < N_COMP; k++) {
            uint32_t b = d_threefry_xor(kc0, kc1, 0u, e0 + (uint32_t)k);
            float u = __uint_as_float((b >> 9) | 0x3f800000u) - 1.0f;
            u = fmaxf(u, TINY);
            float g = -logf(-logf(u));
            float s = g + logit_sh[k];
            if (s > best) { best = s; best_k = k; }
        }
    }

    // ---- normals: z_f = sqrt(2) * erfinv(u*2 - 0.99999994) ----
    float z[32];
    uint32_t e1 = (uint32_t)n * 32u;
#pragma unroll 4
    for (int f = 0; f < 32; f++) {
        uint32_t b = d_threefry_xor(kz0, kz1, 0u, e1 + (uint32_t)f);
        float u = __uint_as_float((b >> 9) | 0x3f800000u) - 1.0f;
        float x = fmaxf(u * 2.0f + (-0.99999994f), -0.99999994f);
        z[f] = 1.41421356237309515f * erfinv_fast(x);
    }

    // ---- out[n,f] = mean[idx,f] + sum_{j<=f} L[idx][f][j] z[j] ----
    const int lbase = best_k * LSTRIDE;
    const int mbase = best_k * MSTRIDE;
    float* outp = out + (size_t)n * N_FEAT;
    int tri = 0;
#pragma unroll
    for (int f0 = 0; f0 < 32; f0 += 4) {
        float acc[4];
#pragma unroll
        for (int q = 0; q < 4; q++) {
            int f = f0 + q;
            float a = mean_sh[mbase + f];
#pragma unroll
            for (int j = 0; j <= f; j++) {
                a = fmaf(z[j], L_sh[lbase + tri + j], a);
            }
            tri += f + 1;
            acc[q] = a;
        }
        __stcs(reinterpret_cast<float4*>(outp + f0),
               make_float4(acc[0], acc[1], acc[2], acc[3]));
    }
}

// -------------------- launch --------------------
extern "C" void kernel_launch(void* const* d_in, const int* in_sizes, int n_in,
                              void* d_out, int out_size) {
    const float* w = nullptr;
    const float* means = nullptr;
    const float* covs = nullptr;
    for (int i = 0; i < n_in; i++) {
        if (in_sizes[i] == N_COMP) w = (const float*)d_in[i];
        else if (in_sizes[i] == N_COMP * N_FEAT) means = (const float*)d_in[i];
        else if (in_sizes[i] == N_COMP * N_FEAT * N_FEAT) covs = (const float*)d_in[i];
    }

    int N = out_size / N_FEAT;

    uint32_t kc0, kc1, kz0, kz1;
    h_threefry(0u, 42u, 0u, 0u, &kc0, &kc1);
    h_threefry(0u, 42u, 0u, 1u, &kz0, &kz1);

    gmm_prep_kernel<<<1, 512>>>(w, covs);

    int blocks = (N + 255) / 256;
    gmm_main_kernel<<<blocks, 256>>>(means, (float*)d_out, N, kc0, kc1, kz0, kz1);
}

// round 4
// speedup vs baseline: 1.3359x; 1.2165x over previous
#include <cuda_runtime.h>
#include <cstdint>
#include <math.h>

// ============================================================================
// GaussianMixtureModel sampling: JAX threefry2x32 (partitionable) +
// categorical (bits-argmax w/ narrow exact tie fixup) + erfinv normals +
// per-component Cholesky. Column-wise fused sampling/matvec (no z[] array).
// ============================================================================

#define N_COMP 16
#define N_FEAT 32

// -------------------- threefry2x32 --------------------
static inline uint32_t h_rotl(uint32_t x, int r) { return (x << r) | (x >> (32 - r)); }

static inline void h_threefry(uint32_t k0, uint32_t k1, uint32_t x0, uint32_t x1,
                              uint32_t* o0, uint32_t* o1) {
    uint32_t k2 = k0 ^ k1 ^ 0x1BD11BDAu;
#define HR_(r) { x0 += x1; x1 = h_rotl(x1, r); x1 ^= x0; }
    x0 += k0; x1 += k1;
    HR_(13) HR_(15) HR_(26) HR_(6)
    x0 += k1; x1 += k2 + 1u;
    HR_(17) HR_(29) HR_(16) HR_(24)
    x0 += k2; x1 += k0 + 2u;
    HR_(13) HR_(15) HR_(26) HR_(6)
    x0 += k0; x1 += k1 + 3u;
    HR_(17) HR_(29) HR_(16) HR_(24)
    x0 += k1; x1 += k2 + 4u;
    HR_(13) HR_(15) HR_(26) HR_(6)
    x0 += k2; x1 += k0 + 5u;
#undef HR_
    *o0 = x0; *o1 = x1;
}

// add on the FMA pipe: d = b*one + a  (one == 1, opaque to ptxas)
__device__ __forceinline__ uint32_t umad1(uint32_t a, uint32_t b, uint32_t one) {
    uint32_t d;
    asm("mad.lo.u32 %0, %1, %2, %3;" : "=r"(d) : "r"(b), "r"(one), "r"(a));
    return d;
}

// Device: returns out0 ^ out1 (partitionable 32-bit random word).
// Round adds routed through IMAD (FMA pipe) to offload the ALU pipe.
__device__ __forceinline__ uint32_t d_threefry_xor(uint32_t k0, uint32_t k1,
                                                   uint32_t x1, uint32_t one) {
    uint32_t k2 = k0 ^ k1 ^ 0x1BD11BDAu;
    uint32_t x0 = 0u;
#define DR_(r) { x0 = umad1(x0, x1, one); x1 = __funnelshift_l(x1, x1, r); x1 ^= x0; }
    x0 += k0; x1 += k1;
    DR_(13) DR_(15) DR_(26) DR_(6)
    x0 += k1; x1 += k2 + 1u;
    DR_(17) DR_(29) DR_(16) DR_(24)
    x0 += k2; x1 += k0 + 2u;
    DR_(13) DR_(15) DR_(26) DR_(6)
    x0 += k0; x1 += k1 + 3u;
    DR_(17) DR_(29) DR_(16) DR_(24)
    x0 += k1; x1 += k2 + 4u;
    DR_(13) DR_(15) DR_(26) DR_(6)
    x0 += k2; x1 += k0 + 5u;
#undef DR_
    return x0 ^ x1;
}

// -------------------- fast erfinv (Giles poly; MUFU log, fma for 1-x^2) ------
__device__ __forceinline__ float erfinv_fast(float x) {
    float w = -__logf(fmaf(-x, x, 1.0f));
    float p;
    if (w < 5.0f) {
        w = w - 2.5f;
        p = 2.81022636e-08f;
        p = fmaf(p, w, 3.43273939e-07f);
        p = fmaf(p, w, -3.5233877e-06f);
        p = fmaf(p, w, -4.39150654e-06f);
        p = fmaf(p, w, 0.00021858087f);
        p = fmaf(p, w, -0.00125372503f);
        p = fmaf(p, w, -0.00417768164f);
        p = fmaf(p, w, 0.246640727f);
        p = fmaf(p, w, 1.50140941f);
    } else {
        w = sqrtf(w) - 3.0f;
        p = -0.000200214257f;
        p = fmaf(p, w, 0.000100950558f);
        p = fmaf(p, w, 0.00134934322f);
        p = fmaf(p, w, -0.00367342844f);
        p = fmaf(p, w, 0.00573950773f);
        p = fmaf(p, w, -0.0076224613f);
        p = fmaf(p, w, 0.00943887047f);
        p = fmaf(p, w, 1.00167406f);
        p = fmaf(p, w, 2.83297682f);
    }
    return p * x;
}

// -------------------- device scratch --------------------
__device__ float g_L[N_COMP * 528];     // packed lower-tri Cholesky
__device__ float g_logits[N_COMP];
__device__ int   g_uniform;

// -------------------- prep kernel --------------------
__global__ void gmm_prep_kernel(const float* __restrict__ w,
                                const float* __restrict__ covs) {
    int warp = threadIdx.x >> 5;
    int lane = threadIdx.x & 31;

    if (threadIdx.x < N_COMP) g_logits[threadIdx.x] = logf(w[threadIdx.x]);
    if (threadIdx.x == 0) {
        int uni = 1;
        for (int k = 1; k < N_COMP; k++)
            if (__float_as_uint(w[k]) != __float_as_uint(w[0])) uni = 0;
        g_uniform = uni;
    }
    if (warp >= N_COMP) return;

    float row[32];
    const float* A = covs + warp * (N_FEAT * N_FEAT) + lane * N_FEAT;
#pragma unroll
    for (int j = 0; j < 32; j++) row[j] = A[j];

#pragma unroll
    for (int j = 0; j < 32; j++) {
        float diag = __shfl_sync(0xffffffffu, row[j], j);
        float Ljj = sqrtf(diag);
        float val = row[j] / Ljj;
        if (lane == j) val = Ljj;
        if (lane < j) val = 0.0f;
        row[j] = val;
#pragma unroll
        for (int m = j + 1; m < 32; m++) {
            float lm = __shfl_sync(0xffffffffu, val, m);
            row[m] -= val * lm;
        }
    }

    int base = warp * 528 + lane * (lane + 1) / 2;
#pragma unroll
    for (int j = 0; j < 32; j++) {
        if (j <= lane) g_L[base + j] = row[j];
    }
}

// -------------------- main kernel --------------------
#define LSTRIDE 529   // 529 mod 32 = 17 -> conflict-free across component idx
#define MSTRIDE 33

__global__ void __launch_bounds__(256, 4)
gmm_main_kernel(const float* __restrict__ means, float* __restrict__ out, int N,
                uint32_t kc0, uint32_t kc1, uint32_t kz0, uint32_t kz1,
                uint32_t one) {
    __shared__ float L_sh[N_COMP * LSTRIDE];
    __shared__ float mean_sh[N_COMP * MSTRIDE];
    __shared__ float logit_sh[N_COMP];
    __shared__ int   uni_sh;

    for (int i = threadIdx.x; i < N_COMP * 528; i += blockDim.x) {
        int k = i / 528, r = i - k * 528;
        L_sh[k * LSTRIDE + r] = g_L[i];
    }
    for (int i = threadIdx.x; i < N_COMP * N_FEAT; i += blockDim.x) {
        mean_sh[(i >> 5) * MSTRIDE + (i & 31)] = means[i];
    }
    if (threadIdx.x < N_COMP) logit_sh[threadIdx.x] = g_logits[threadIdx.x];
    if (threadIdx.x == 0) uni_sh = g_uniform;
    __syncthreads();

    int n = blockIdx.x * blockDim.x + threadIdx.x;
    if (n >= N) return;

    const float TINY = 1.17549435e-38f;
    uint32_t e0 = (uint32_t)n * 16u;
    int best_k;

    if (uni_sh) {
        // bits-argmax (monotone map); first-index tie-break via max/2nd-max.
        uint32_t m1, m2; int j1, j2;
        {
            uint32_t v0 = d_threefry_xor(kc0, kc1, e0, one) >> 9;
            m1 = v0; j1 = 0; m2 = 0u; j2 = 99;
        }
#pragma unroll 5
        for (int k = 1; k < N_COMP; k++) {
            uint32_t v = d_threefry_xor(kc0, kc1, e0 + (uint32_t)k, one) >> 9;
            if (v > m1)      { m2 = m1; j2 = j1; m1 = v; j1 = k; }
            else if (v > m2) { m2 = v; j2 = k; }
        }
        best_k = j1;
        // Rounded-score inversion needs raw-bit gap <~2 (|ds/dv| >= 3.2e-7 vs
        // ~2ulp error). Threshold 64 = 30x margin, fires w/ P~1e-4.
        if (j2 < j1 && (m1 - m2) < 64u) {
            float u1 = fmaxf(__uint_as_float(m1 | 0x3f800000u) - 1.0f, TINY);
            float u2 = fmaxf(__uint_as_float(m2 | 0x3f800000u) - 1.0f, TINY);
            float s1 = -logf(-logf(u1)) + logit_sh[j1];
            float s2 = -logf(-logf(u2)) + logit_sh[j2];
            if (s2 >= s1) best_k = j2;
        }
    } else {
        // general weights: full gumbel argmax
        best_k = 0;
        float best = __int_as_float(0xff800000);
#pragma unroll 4
        for (int k = 0; k < N_COMP; k++) {
            uint32_t b = d_threefry_xor(kc0, kc1, e0 + (uint32_t)k, one);
            float u = __uint_as_float((b >> 9) | 0x3f800000u) - 1.0f;
            u = fmaxf(u, TINY);
            float s = -logf(-logf(u)) + logit_sh[k];
            if (s > best) { best = s; best_k = k; }
        }
    }

    // ---- column-wise fused: acc[f] = mean[k,f] + sum_j L[k][f][j] * z_j ----
    const int lbase = best_k * LSTRIDE;
    const int mbase = best_k * MSTRIDE;
    float acc[32];
#pragma unroll
    for (int f = 0; f < 32; f++) acc[f] = mean_sh[mbase + f];

    uint32_t e1 = (uint32_t)n * 32u;
#pragma unroll
    for (int j = 0; j < 32; j++) {
        uint32_t b = d_threefry_xor(kz0, kz1, e1 + (uint32_t)j, one);
        float u = __uint_as_float((b >> 9) | 0x3f800000u) - 1.0f;
        float x = fmaxf(u * 2.0f + (-0.99999994f), -0.99999994f);
        float zj = 1.41421356237309515f * erfinv_fast(x);
        // packed triangular column j: element (f,j) at tri(f)+j
#pragma unroll
        for (int f = j; f < 32; f++) {
            acc[f] = fmaf(zj, L_sh[lbase + (f * (f + 1)) / 2 + j], acc[f]);
        }
    }

    float* outp = out + (size_t)n * N_FEAT;
#pragma unroll
    for (int f0 = 0; f0 < 32; f0 += 4) {
        __stcs(reinterpret_cast<float4*>(outp + f0),
               make_float4(acc[f0], acc[f0 + 1], acc[f0 + 2], acc[f0 + 3]));
    }
}

// -------------------- launch --------------------
extern "C" void kernel_launch(void* const* d_in, const int* in_sizes, int n_in,
                              void* d_out, int out_size) {
    const float* w = nullptr;
    const float* means = nullptr;
    const float* covs = nullptr;
    for (int i = 0; i < n_in; i++) {
        if (in_sizes[i] == N_COMP) w = (const float*)d_in[i];
        else if (in_sizes[i] == N_COMP * N_FEAT) means = (const float*)d_in[i];
        else if (in_sizes[i] == N_COMP * N_FEAT * N_FEAT) covs = (const float*)d_in[i];
    }

    int N = out_size / N_FEAT;

    uint32_t kc0, kc1, kz0, kz1;
    h_threefry(0u, 42u, 0u, 0u, &kc0, &kc1);
    h_threefry(0u, 42u, 0u, 1u, &kz0, &kz1);

    gmm_prep_kernel<<<1, 512>>>(w, covs);

    int blocks = (N + 255) / 256;
    gmm_main_kernel<<<blocks, 256>>>(means, (float*)d_out, N, kc0, kc1, kz0, kz1, 1u);
}